// round 17
// baseline (speedup 1.0000x reference)
#include <cuda_runtime.h>
#include <cuda_fp16.h>

// SU2Attention: batch=1, seq=2048, heads=8, spinor_dim=2 (complex).
// Per head: Q=K are 4-dim real unit vectors u_j = s_j/||s_j||, logits u_i.u_j
// scaled by 1/sqrt(2) (bounded -> no max subtraction), softmax over keys,
// values are raw 4-vectors s_j.
//
// Output layout (verified R5-R16): PLANAR — real plane (2048*8*2 floats) then
// imag plane. d_in[0]=real, d_in[1]=imag.
//
// R17: fragment-packed mainloop. R16 showed the tensor path is issue-bound
// with 4 scattered LDS.32 + addressing per iteration. Since every q-subtile
// warp consumes the SAME B-fragment stream, preload now packs each lane's
// {b0, b1, vb0, vb1} into a lane-major uint4 buffer -> mainloop does ONE
// LDS.128 + 2 S-mma + cvt/ex2 + 1 PV-mma (~13 slots vs ~20). PV accumulation
// alternates two C fragments to break the serial HMMA chain.

#define SEQ     2048
#define HEADS   8
#define QTILE   128
#define BLOCK   1024
#define KQUART  4                   // key quarters (one per warp group)
#define KCHUNK  (SEQ / KQUART)      // 512 keys
#define NITER   (KCHUNK / 16)       // 32 iterations
#define NCHUNK  (SEQ / 16)          // 128 fragment chunks
#define VSTR    2056                // padded value-plane stride (halves)

// ---- smem byte offsets (single dynamic buffer, 16B-aligned carve) ----
#define SK_OFF  0                       // skey : 2048 rows x 16B            32768
#define SQ_OFF  32768                   // squ  : 128 rows x 16B              2048
#define VP_OFF  34816                   // planes: 8 x VSTR halves           32896
#define FR_OFF  67712                   // frag : 128 x 32 x 16B             65536
#define SA_OFF  133248                  // sacc : 4 x 8 x 16 x 8 f32         16384
#define SM_TOT  149632

__device__ __forceinline__ unsigned cvt_f16x2(float hi, float lo) {
    unsigned d;
    asm("cvt.rn.f16x2.f32 %0, %1, %2;" : "=r"(d) : "f"(hi), "f"(lo));
    return d;
}

__device__ __forceinline__ unsigned hexp2_2(unsigned x) {
    unsigned r;
    asm("ex2.approx.f16x2 %0, %1;" : "=r"(r) : "r"(x));
    return r;
}

__device__ __forceinline__ void mma_s(float* c, unsigned a0, unsigned a1, unsigned b0) {
    float z = 0.f;
    asm("mma.sync.aligned.m16n8k8.row.col.f32.f16.f16.f32 "
        "{%0,%1,%2,%3}, {%4,%5}, {%6}, {%7,%8,%9,%10};"
        : "=f"(c[0]), "=f"(c[1]), "=f"(c[2]), "=f"(c[3])
        : "r"(a0), "r"(a1), "r"(b0), "f"(z), "f"(z), "f"(z), "f"(z));
}

__device__ __forceinline__ void mma_pv(float* c, unsigned p0, unsigned p1,
                                       unsigned p2, unsigned p3,
                                       unsigned b0, unsigned b1) {
    asm("mma.sync.aligned.m16n8k16.row.col.f32.f16.f16.f32 "
        "{%0,%1,%2,%3}, {%4,%5,%6,%7}, {%8,%9}, {%0,%1,%2,%3};"
        : "+f"(c[0]), "+f"(c[1]), "+f"(c[2]), "+f"(c[3])
        : "r"(p0), "r"(p1), "r"(p2), "r"(p3), "r"(b0), "r"(b1));
}

__global__ __launch_bounds__(BLOCK, 1)
void su2_attn_kernel(const float* __restrict__ p0,   // spinors_real
                     const float* __restrict__ p1,   // spinors_imag
                     float* __restrict__ out) {
    extern __shared__ char smem[];
    uint4*  skey   = reinterpret_cast<uint4*>(smem + SK_OFF);  // [2048]
    uint4*  squ    = reinterpret_cast<uint4*>(smem + SQ_OFF);  // [128]
    __half* planes = reinterpret_cast<__half*>(smem + VP_OFF); // [8][VSTR]
    uint4*  frag   = reinterpret_cast<uint4*>(smem + FR_OFF);  // [128][32]
    float*  sacc   = reinterpret_cast<float*>(smem + SA_OFF);  // [4][8][16][8]

    const int h   = blockIdx.y;
    const int q0  = blockIdx.x * QTILE;
    const int tid = threadIdx.x;

    // SCALE * log2(e), folded into the queries so P = ex2(S).
    const float C = 0.70710678118654752f * 1.44269504088896341f;

    // ---- Phase 1: normalize keys, build key rows + value planes ----
    for (int j = tid; j < SEQ; j += BLOCK) {
        const int base = (j * HEADS + h) * 2;
        float2 a = *reinterpret_cast<const float2*>(p0 + base);  // re (d0,d1)
        float2 b = *reinterpret_cast<const float2*>(p1 + base);  // im (d0,d1)
        float x = a.x, y = a.y, z = b.x, w = b.y;
        float rn = rsqrtf(x*x + y*y + z*z + w*w);
        uint4 kr;
        kr.x = cvt_f16x2(y * rn, x * rn);   // {lo=ux, hi=uy}
        kr.y = cvt_f16x2(w * rn, z * rn);   // {lo=uz, hi=uw}
        kr.z = 0u;
        kr.w = 0u;
        skey[j] = kr;
        planes[0 * VSTR + j] = __float2half(x);
        planes[1 * VSTR + j] = __float2half(y);
        planes[2 * VSTR + j] = __float2half(z);
        planes[3 * VSTR + j] = __float2half(w);
        planes[4 * VSTR + j] = __float2half(1.0f);   // denominator column
        planes[5 * VSTR + j] = __half(0.0f);
        planes[6 * VSTR + j] = __half(0.0f);
        planes[7 * VSTR + j] = __half(0.0f);
        if (j >= q0 && j < q0 + QTILE) {
            float rc = rn * C;
            uint4 qr;
            qr.x = cvt_f16x2(y * rc, x * rc);
            qr.y = cvt_f16x2(w * rc, z * rc);
            qr.z = 0u;
            qr.w = 0u;
            squ[j - q0] = qr;
        }
    }
    __syncthreads();

    // ---- Phase 2: pack per-lane B fragments {b0, b1, vb0, vb1} ----
    // Bit-identical to the words the mainloop previously loaded scattered.
    for (int e = tid; e < NCHUNK * 32; e += BLOCK) {
        const int c  = e >> 5;
        const int ln = e & 31;
        const int g2 = ln >> 2;
        const int lm = ln & 3;
        const int kb = c << 4;
        const unsigned* kr0 = reinterpret_cast<const unsigned*>(&skey[kb + g2]);
        const unsigned* kr1 = reinterpret_cast<const unsigned*>(&skey[kb + 8 + g2]);
        uint4 f;
        f.x = kr0[lm];                      // K[2l..2l+1][kb+g]  (0 for lm>=2)
        f.y = kr1[lm];                      // K[2l..2l+1][kb+8+g]
        f.z = *reinterpret_cast<const unsigned*>(planes + g2 * VSTR + kb + 2 * lm);
        f.w = *reinterpret_cast<const unsigned*>(planes + g2 * VSTR + kb + 8 + 2 * lm);
        frag[e] = f;
    }
    __syncthreads();

    // ---- Mainloop: warp = (q-subtile sq of 16 queries, key-quarter kh) ----
    const int lane = tid & 31;
    const int warp = tid >> 5;
    const int sq   = warp & 7;          // 0..7 -> queries sq*16..+15
    const int kh   = warp >> 3;         // 0..3 -> keys kh*512..+511
    const int lam  = lane & 3;
    const int g    = lane >> 2;

    // A fragment (m16n8k8, row-major): a0 = Q[g][2l..2l+1], a1 = Q[g+8][...]
    const unsigned a0 = *reinterpret_cast<const unsigned*>(
        smem + SQ_OFF + (sq * 16 + g) * 16 + lam * 4);
    const unsigned a1 = *reinterpret_cast<const unsigned*>(
        smem + SQ_OFF + (sq * 16 + g + 8) * 16 + lam * 4);

    float accA[4] = {0.f, 0.f, 0.f, 0.f};
    float accB[4] = {0.f, 0.f, 0.f, 0.f};
    const uint4* fbase = frag + (kh * NITER) * 32 + lane;

    #pragma unroll 8
    for (int c = 0; c < NITER; ++c) {
        uint4 f = fbase[c * 32];            // one LDS.128, conflict-free
        float C0[4], C1[4];
        mma_s(C0, a0, a1, f.x);             // S cols kb..kb+7
        mma_s(C1, a0, a1, f.y);             // S cols kb+8..kb+15
        unsigned pp0 = hexp2_2(cvt_f16x2(C0[1], C0[0]));
        unsigned pp1 = hexp2_2(cvt_f16x2(C0[3], C0[2]));
        unsigned pp2 = hexp2_2(cvt_f16x2(C1[1], C1[0]));
        unsigned pp3 = hexp2_2(cvt_f16x2(C1[3], C1[2]));
        if (c & 1)
            mma_pv(accB, pp0, pp1, pp2, pp3, f.z, f.w);
        else
            mma_pv(accA, pp0, pp1, pp2, pp3, f.z, f.w);
    }
    #pragma unroll
    for (int i = 0; i < 4; ++i) accA[i] += accB[i];

    // ---- Epilogue: stash C frags, combine key-quarters, normalize, store ----
    {
        float* sa = sacc + ((kh * 8 + sq) * 16) * 8;
        sa[g * 8 + 2 * lam]           = accA[0];
        sa[g * 8 + 2 * lam + 1]       = accA[1];
        sa[(g + 8) * 8 + 2 * lam]     = accA[2];
        sa[(g + 8) * 8 + 2 * lam + 1] = accA[3];
    }
    __syncthreads();

    if (tid < QTILE) {
        const int q  = tid;
        const int ts = q >> 4;              // sub-tile
        const int r  = q & 15;              // row in sub-tile
        float vx = 0.f, vy = 0.f, vz = 0.f, vw = 0.f, dn = 0.f;
        #pragma unroll
        for (int k = 0; k < KQUART; ++k) {
            const float* A = sacc + ((k * 8 + ts) * 16 + r) * 8;
            vx += A[0]; vy += A[1]; vz += A[2]; vw += A[3]; dn += A[4];
        }
        const float inv = __frcp_rn(dn);
        const int ohd = (q0 + q) * HEADS + h;
        // planar complex: real plane then imag plane, each (1,2048,8,2)
        *reinterpret_cast<float2*>(out + ohd * 2) =
            make_float2(vx * inv, vy * inv);
        *reinterpret_cast<float2*>(out + SEQ * HEADS * 2 + ohd * 2) =
            make_float2(vz * inv, vw * inv);
    }
}

extern "C" void kernel_launch(void* const* d_in, const int* in_sizes, int n_in,
                              void* d_out, int out_size) {
    const float* p0 = (const float*)d_in[0];
    const float* p1 = (const float*)d_in[1];
    float* out = (float*)d_out;

    cudaFuncSetAttribute(su2_attn_kernel,
                         cudaFuncAttributeMaxDynamicSharedMemorySize, SM_TOT);

    dim3 grid(SEQ / QTILE, HEADS);      // 16 x 8 = 128 blocks
    dim3 block(BLOCK);
    su2_attn_kernel<<<grid, block, SM_TOT>>>(p0, p1, out);
}